// round 16
// baseline (speedup 1.0000x reference)
#include <cuda_runtime.h>

#define BQ 2
#define NPTS 512
#define INDIM 512
#define MEMD 300
#define HIDD 64
#define NEG 0.01f
#define NN (NPTS*NPTS)

typedef unsigned long long ull;

// ---------------- scratch ----------------
__device__ float g_hp0[1024*MEMD], g_hp1[1024*MEMD], g_hp2[1024*MEMD], g_hp3[1024*MEMD];
__device__ float g_h [1024*MEMD];                      // combined h
__device__ float g_sp0[1024*128],  g_sp1[1024*128],  g_sp2[1024*128],  g_sp3[1024*128];
__device__ float g_op0[1024*MEMD], g_op1[1024*MEMD], g_op2[1024*MEMD], g_op3[1024*MEMD];
__device__ float g_f [1024*MEMD];                      // layer-0 output (combined+scaled)
__device__ float g_u [BQ*NN];
__device__ float g_sum[4];                             // [layer][batch]

// ---------------- f32x2 helpers ----------------
__device__ __forceinline__ ull dup2(float x) {
    ull r; asm("mov.b64 %0, {%1,%1};" : "=l"(r) : "f"(x)); return r;
}
__device__ __forceinline__ void ffma2(ull& d, ull a, ull b) {
    asm("fma.rn.f32x2 %0, %1, %2, %0;" : "+l"(d) : "l"(a), "l"(b));
}
__device__ __forceinline__ float2 unpk(ull v) {
    float2 r; asm("mov.b64 {%0,%1}, %2;" : "=f"(r.x), "=f"(r.y) : "l"(v)); return r;
}

// ---------------- cp.async helpers ----------------
__device__ __forceinline__ unsigned s2u(const void* p) {
    return (unsigned)__cvta_generic_to_shared(p);
}
__device__ __forceinline__ void cpa4(unsigned dst, const void* src, int sz) {
    asm volatile("cp.async.ca.shared.global [%0], [%1], 4, %2;"
                 :: "r"(dst), "l"(src), "r"(sz));
}
__device__ __forceinline__ void cpa16(unsigned dst, const void* src, int sz) {
    asm volatile("cp.async.ca.shared.global [%0], [%1], 16, %2;"
                 :: "r"(dst), "l"(src), "r"(sz));
}
__device__ __forceinline__ void cp_commit() {
    asm volatile("cp.async.commit_group;");
}
__device__ __forceinline__ void cp_wait1() {
    asm volatile("cp.async.wait_group 1;");
}

// ====== GEMM core: 64x64 tile, 256 thr, 4x4 micro, f32x2, cp.async 3-stage ======
__device__ __forceinline__ void gemm64cp(
    const float* __restrict__ A, int lda, int ar0, int klo, int khi,
    const float* __restrict__ B, int ldb, int bc0, int bcmax,
    float* __restrict__ C, int ldc, int cr0, int cc0, int ccmax,
    const float* __restrict__ bias, float cscale)
{
    __shared__ __align__(16) float As[3][16*68];   // [st][k][row]
    __shared__ __align__(16) float Bs[3][16*68];   // [st][k][col]
    int tid = threadIdx.x;
    int tx = tid & 15, ty = tid >> 4;
    int ty4 = ty*4, tx4 = tx*4;
    int kA = tid & 15, rA = tid >> 4;
    int qB = tid & 15, kB = tid >> 4;
    int bq = bc0 + qB*4;
    int bsz = (bcmax - bq) * 4;
    bsz = bsz < 0 ? 0 : (bsz > 16 ? 16 : bsz);
    int bqc = min(bq, bcmax - 4);
    ull acc[4][2] = {};
    int nch = (khi - klo + 15) >> 4;

    auto issue = [&](int c, int st) {
        int k0 = klo + c*16;
        int ka = k0 + kA;
        int asz = (ka < khi) ? 4 : 0;
        int kac = min(ka, khi - 1);
        #pragma unroll
        for (int p = 0; p < 4; p++)
            cpa4(s2u(&As[st][kA*68 + rA + 16*p]),
                 &A[(size_t)(ar0 + rA + 16*p)*lda + kac], asz);
        int kb = k0 + kB;
        int kbc = min(kb, khi - 1);
        cpa16(s2u(&Bs[st][kB*68 + qB*4]),
              &B[(size_t)kbc*ldb + bqc], (kb < khi) ? bsz : 0);
    };

    issue(0, 0); cp_commit();
    if (nch > 1) { issue(1, 1); } cp_commit();
    for (int c = 0; c < nch; c++) {
        cp_wait1();
        __syncthreads();
        if (c + 2 < nch) { issue(c + 2, (c + 2) % 3); }
        cp_commit();
        const float* as = As[c % 3];
        const float* bs = Bs[c % 3];
        #pragma unroll
        for (int k = 0; k < 16; k++) {
            float4 av = *(const float4*)&as[k*68 + ty4];
            ulonglong2 bv = *(const ulonglong2*)&bs[k*68 + tx4];
            ull a0 = dup2(av.x), a1 = dup2(av.y), a2 = dup2(av.z), a3 = dup2(av.w);
            ffma2(acc[0][0], a0, bv.x); ffma2(acc[0][1], a0, bv.y);
            ffma2(acc[1][0], a1, bv.x); ffma2(acc[1][1], a1, bv.y);
            ffma2(acc[2][0], a2, bv.x); ffma2(acc[2][1], a2, bv.y);
            ffma2(acc[3][0], a3, bv.x); ffma2(acc[3][1], a3, bv.y);
        }
    }
    int cc = cc0 + tx4;
    if (cc < ccmax) {
        float4 bb = bias ? *(const float4*)&bias[cc] : make_float4(0.f,0.f,0.f,0.f);
        #pragma unroll
        for (int r = 0; r < 4; r++) {
            float2 lo = unpk(acc[r][0]), hi = unpk(acc[r][1]);
            float4 v = make_float4(lo.x*cscale + bb.x, lo.y*cscale + bb.y,
                                   hi.x*cscale + bb.z, hi.y*cscale + bb.w);
            *(float4*)&C[(size_t)(cr0 + ty4 + r)*ldc + cc] = v;
        }
    }
}

__device__ float* hp_buf(int sp) {
    return sp == 0 ? g_hp0 : sp == 1 ? g_hp1 : sp == 2 ? g_hp2 : g_hp3;
}
__device__ float* sp_buf(int sp) {
    return sp == 0 ? g_sp0 : sp == 1 ? g_sp1 : sp == 2 ? g_sp2 : g_sp3;
}
__device__ float* op_buf(int sp) {
    return sp == 0 ? g_op0 : sp == 1 ? g_op1 : sp == 2 ? g_op2 : g_op3;
}

// ====== h partials = A @ W (+bias on sp0)  grid (5, 16, 4) = 320 CTAs ======
__global__ void __launch_bounds__(256) k_h(
    const float* __restrict__ Aext, int use_gf,
    const float* __restrict__ W, const float* __restrict__ bias,
    int Ktot, int lay)
{
    int sp = blockIdx.z;
    if (sp == 0 && blockIdx.x == 0 && blockIdx.y == 0 && threadIdx.x < 2)
        g_sum[lay*2 + threadIdx.x] = 0.f;
    int kq = (Ktot + 3) >> 2;
    int klo = sp * kq, khi = min(Ktot, klo + kq);
    const float* A = use_gf ? g_f : Aext;
    int lda = use_gf ? MEMD : Ktot;
    gemm64cp(A, lda, blockIdx.y*64, klo, khi,
             W, MEMD, blockIdx.x*64, MEMD,
             hp_buf(sp), MEMD, blockIdx.y*64, blockIdx.x*64, MEMD,
             sp == 0 ? bias : (const float*)0, 1.f);
}

// ====== comb_h: g_h = hp0+hp1+hp2+hp3  grid 300 x 256 ======
__global__ void __launch_bounds__(256) comb_h()
{
    int t4 = blockIdx.x * 256 + threadIdx.x;
    float4 a = *(const float4*)&g_hp0[(size_t)t4*4];
    float4 b = *(const float4*)&g_hp1[(size_t)t4*4];
    float4 c = *(const float4*)&g_hp2[(size_t)t4*4];
    float4 d = *(const float4*)&g_hp3[(size_t)t4*4];
    float4 v = make_float4((a.x+b.x)+(c.x+d.x), (a.y+b.y)+(c.y+d.y),
                           (a.z+b.z)+(c.z+d.z), (a.w+b.w)+(c.w+d.w));
    *(float4*)&g_h[(size_t)t4*4] = v;
}

// ====== s partials = g_h @ a1w_half (+a1b on ct0/sp0)  grid (2, 16, 4) ======
__global__ void __launch_bounds__(256) k_s(
    const float* __restrict__ a1w, const float* __restrict__ a1b)
{
    int ct = blockIdx.x, sp = blockIdx.z;
    int kq = (MEMD + 3) >> 2;                      // 75
    int klo = sp * kq, khi = min(MEMD, klo + kq);
    gemm64cp(g_h, MEMD, blockIdx.y*64, klo, khi,
             a1w + (size_t)ct*MEMD*HIDD, HIDD, 0, HIDD,
             sp_buf(sp), 128, blockIdx.y*64, ct*64, 128,
             (ct == 0 && sp == 0) ? a1b : (const float*)0, 1.f);
}

// ====== u = exp(masked leaky(e)) + batch sum ======
// 32i x 64j tiles, 256 thr, grid (8, 16, 2) = 256 CTAs (all SMs covered, 2x warps)
__global__ void __launch_bounds__(256) k_e(
    const float* __restrict__ adj, const float* __restrict__ a2w,
    const float* __restrict__ a2b, int lay)
{
    __shared__ __align__(16) float Si[64*36];      // [h][i_local 0..31]
    __shared__ __align__(16) float Sj[64*68];      // [h][j_local 0..63]
    __shared__ float Wv[64];
    __shared__ float red[256];
    int tid = threadIdx.x;
    int tx = tid & 15, ty = tid >> 4;              // tx: j-quad(16), ty: i-pair(16)
    int b = blockIdx.z;
    int i0 = blockIdx.y * 32, j0 = blockIdx.x * 64;
    if (tid < 64) Wv[tid] = a2w[tid];
    #pragma unroll
    for (int p = 0; p < 8; p++) {                  // Si: 2048 elems, h-fast coalesced
        int idx = tid + p*256;
        int h = idx & 63, r = idx >> 6;            // r 0..31
        size_t o = (size_t)(b*NPTS + i0 + r)*128 + h;
        Si[h*36 + r] = (g_sp0[o] + g_sp1[o]) + (g_sp2[o] + g_sp3[o]);
    }
    #pragma unroll
    for (int p = 0; p < 16; p++) {                 // Sj: 4096 elems
        int idx = tid + p*256;
        int h = idx & 63, r = idx >> 6;            // r 0..63
        size_t o = (size_t)(b*NPTS + j0 + r)*128 + 64 + h;
        Sj[h*68 + r] = (g_sp0[o] + g_sp1[o]) + (g_sp2[o] + g_sp3[o]);
    }
    __syncthreads();
    float acc[2][4] = {};
    int i_l = ty*2, j_l = tx*4;
    #pragma unroll 4
    for (int h = 0; h < 64; h++) {
        float w = Wv[h];
        float2 si = *(const float2*)&Si[h*36 + i_l];
        float4 sj = *(const float4*)&Sj[h*68 + j_l];
        float siv[2] = {si.x, si.y};
        float sjv[4] = {sj.x, sj.y, sj.z, sj.w};
        #pragma unroll
        for (int di = 0; di < 2; di++)
            #pragma unroll
            for (int dj = 0; dj < 4; dj++)
                acc[di][dj] = fmaf(fmaxf(siv[di] + sjv[dj], 0.f), w, acc[di][dj]);
    }
    float ab = a2b[0];
    float lsum = 0.f;
    #pragma unroll
    for (int di = 0; di < 2; di++) {
        int i = i0 + i_l + di;
        float4 av = *(const float4*)&adj[(size_t)(b*NPTS + i)*NPTS + j0 + j_l];
        float am[4] = {av.x, av.y, av.z, av.w};
        float o[4];
        #pragma unroll
        for (int dj = 0; dj < 4; dj++) {
            float e = acc[di][dj] + ab;
            e = (e > 0.f) ? e : NEG * e;
            float lg = e * am[dj] + (1.f - am[dj]) * (-1e30f);
            o[dj] = __expf(lg);                    // masked -> exactly 0
        }
        *(float4*)&g_u[(size_t)b*NN + i*NPTS + j0 + j_l] =
            make_float4(o[0], o[1], o[2], o[3]);
        lsum += (o[0] + o[1]) + (o[2] + o[3]);
    }
    red[tid] = lsum;
    __syncthreads();
    for (int s = 128; s > 0; s >>= 1) {
        if (tid < s) red[tid] += red[tid + s];
        __syncthreads();
    }
    if (tid == 0) atomicAdd(&g_sum[lay*2 + b], red[0]);
}

// ====== out partials = U @ g_h[b]  grid (5, 8, 8: b*4+split) = 320 CTAs ======
__global__ void __launch_bounds__(256) k_out()
{
    int b = blockIdx.z >> 2, sp = blockIdx.z & 3;
    int klo = sp * 128, khi = klo + 128;
    gemm64cp(g_u + (size_t)b*NN, NPTS, blockIdx.y*64, klo, khi,
             g_h + (size_t)b*NPTS*MEMD, MEMD, blockIdx.x*64, MEMD,
             op_buf(sp), MEMD, b*NPTS + blockIdx.y*64, blockIdx.x*64, MEMD,
             (const float*)0, 1.f);
}

// ====== k_comb: dst = (Σop) * (1/g_sum[lay*2+b]) ======
__global__ void __launch_bounds__(256) k_comb(float* __restrict__ out_ext,
                                              int to_gf, int lay)
{
    float* dst = to_gf ? g_f : out_ext;
    int t4 = blockIdx.x * 256 + threadIdx.x;
    int row = t4 / 75;
    float inv = 1.f / g_sum[lay*2 + (row >> 9)];
    float4 a = *(const float4*)&g_op0[(size_t)t4*4];
    float4 b = *(const float4*)&g_op1[(size_t)t4*4];
    float4 c = *(const float4*)&g_op2[(size_t)t4*4];
    float4 d = *(const float4*)&g_op3[(size_t)t4*4];
    float4 v = make_float4(((a.x+b.x)+(c.x+d.x))*inv, ((a.y+b.y)+(c.y+d.y))*inv,
                           ((a.z+b.z)+(c.z+d.z))*inv, ((a.w+b.w)+(c.w+d.w))*inv);
    *(float4*)&dst[(size_t)t4*4] = v;
}

// ---------------- host ----------------
extern "C" void kernel_launch(void* const* d_in, const int* in_sizes, int n_in,
                              void* d_out, int out_size) {
    const float* feature = (const float*)d_in[0];
    const float* adj     = (const float*)d_in[1];
    const float* w0      = (const float*)d_in[2];
    const float* b0      = (const float*)d_in[3];
    const float* w1      = (const float*)d_in[4];
    const float* b1      = (const float*)d_in[5];
    const float* a1w     = (const float*)d_in[6];
    const float* a1b     = (const float*)d_in[7];
    const float* a2w     = (const float*)d_in[8];
    const float* a2b     = (const float*)d_in[9];
    float* out = (float*)d_out;

    dim3 gh(5, 16, 4);       // 320 CTAs
    dim3 gs(2, 16, 4);       // 128 CTAs
    dim3 ge(8, 16, BQ);      // 256 CTAs x 256 thr  (32i x 64j tiles)
    dim3 go(5, 8, 8);        // 320 CTAs

    // ---- layer 0 ----
    k_h   <<<gh, 256>>>(feature, 0, w0, b0, INDIM, 0);
    comb_h<<<300, 256>>>();
    k_s   <<<gs, 256>>>(a1w, a1b);
    k_e   <<<ge, 256>>>(adj, a2w, a2b, 0);
    k_out <<<go, 256>>>();
    k_comb<<<300, 256>>>(out, 1, 0);               // -> g_f

    // ---- layer 1 ----
    k_h   <<<gh, 256>>>(nullptr, 1, w1, b1, MEMD, 1);
    comb_h<<<300, 256>>>();
    k_s   <<<gs, 256>>>(a1w, a1b);
    k_e   <<<ge, 256>>>(adj, a2w, a2b, 1);
    k_out <<<go, 256>>>();
    k_comb<<<300, 256>>>(out, 0, 1);               // -> d_out
}